// round 14
// baseline (speedup 1.0000x reference)
#include <cuda_runtime.h>

// Problem constants
#define GRID_M     96
#define NUM_NODES  9216          // 96*96
#define MAX_EDGES  36864         // 4*NUM_NODES
#define IMG_W      192
#define MASK_ELEMS 84934656     // 9216*9216
#define NBLK       36            // blocks of 1024 threads; all co-resident

typedef unsigned long long u64;

// Scratch (no allocations, no resets needed):
// g_gen: monotonic; all 36 blocks of one call compute the same gen = ticket/36.
// Publications are single 64-bit words ((gen+1)<<32 | payload): generation tag
// makes stale values self-identifying -> no reset choreography.
__device__ unsigned int g_gen;        // init 0
__device__ u64 g_pub_min[NBLK];
__device__ u64 g_pub_max[NBLK];
__device__ u64 g_pub_cnt[NBLK];

__device__ __forceinline__ u64 vload64(const u64* p) {
    return *((volatile const u64*)p);
}

// 2x2 max-pool of pooled cell (i,j): bit-identical everywhere.
__device__ __forceinline__ float poolv(const float* __restrict__ dc, int i, int j) {
    const float2* r0 = reinterpret_cast<const float2*>(dc + (2 * i) * IMG_W);
    const float2* r1 = reinterpret_cast<const float2*>(dc + (2 * i + 1) * IMG_W);
    float2 a = r0[j];
    float2 c = r1[j];
    return fmaxf(fmaxf(a.x, a.y), fmaxf(c.x, c.y));
}

// --------------------------------------------------------------------------
// One fused kernel: 36 blocks x 1024 threads.
// Thread t: node l = b*256 + t/4, neighbor k = t%4 in ascending-column order
//   k=0:(-1,-1)  k=1:(-1,+1)  k=2:(+1,-1)  k=3:(+1,+1)
// Warp ballot bit order == jnp.nonzero enumeration order within the warp.
// --------------------------------------------------------------------------
__global__ __launch_bounds__(1024, 1)
void k_fused(const float* __restrict__ dc, const float* __restrict__ noise,
             const unsigned int* __restrict__ mask, float* __restrict__ out) {
    __shared__ float    smn[32], smx[32];
    __shared__ int      sws[32];
    __shared__ float    s_th;
    __shared__ int      s_base;
    __shared__ unsigned s_gen;

    const int b    = blockIdx.x;
    const int t    = threadIdx.x;
    const int lane = t & 31;
    const int w    = t >> 5;
    const int nb   = t >> 2;               // node-in-block 0..255
    const int k    = t & 3;                // neighbor index
    const int l    = b * 256 + nb;         // node id 0..9215
    const int i    = l / GRID_M;
    const int j    = l - i * GRID_M;

    if (t == 0) s_gen = atomicAdd(&g_gen, 1u) / NBLK;

    // ---- neighbor coords ----
    const int di = (k >> 1) ? 1 : -1;
    const int dj = (k & 1)  ? 1 : -1;
    const int ni = i + di;
    const int nj = j + dj;
    const bool valid = (ni >= 0) & (ni < GRID_M) & (nj >= 0) & (nj < GRID_M);
    const int nl = ni * GRID_M + nj;       // = l +/- 95 / 97

    // ---- independent loads, issued up front ----
    unsigned mw = 0;
    if (valid) mw = mask[(unsigned)l * (unsigned)NUM_NODES + (unsigned)nl];

    const float v  = poolv(dc, i, j);      // own pooled value (pre-noise)
    const float dv = v + noise[l];
    float ndv = 0.f;
    if (valid) ndv = poolv(dc, ni, nj) + noise[nl];

    // ---- sentinel fill: 36864 float2 slots, 1024/block ----
    {
        float2 s2 = make_float2((float)NUM_NODES, (float)NUM_NODES);
        reinterpret_cast<float2*>(out)[b * 1024 + t] = s2;
    }

    // ---- block min/max of pooled values (4x-redundant per node: harmless) ----
    {
        float mn = v, mx = v;
#pragma unroll
        for (int o = 16; o; o >>= 1) {
            mn = fminf(mn, __shfl_xor_sync(0xffffffffu, mn, o));
            mx = fmaxf(mx, __shfl_xor_sync(0xffffffffu, mx, o));
        }
        if (lane == 0) { smn[w] = mn; smx[w] = mx; }
    }
    __syncthreads();                        // also publishes s_gen

    const u64 tag = ((u64)(s_gen + 1)) << 32;

    // ---- warp 0: fold partials, publish tagged min/max, poll, threshold ----
    if (w == 0) {
        float mn = smn[lane], mx = smx[lane];
#pragma unroll
        for (int o = 16; o; o >>= 1) {
            mn = fminf(mn, __shfl_xor_sync(0xffffffffu, mn, o));
            mx = fmaxf(mx, __shfl_xor_sync(0xffffffffu, mx, o));
        }
        if (lane == 0) {
            g_pub_min[b] = tag | (u64)(unsigned)__float_as_int(mn);
            g_pub_max[b] = tag | (u64)(unsigned)__float_as_int(mx);
        }
        const int e2 = lane + 32;           // lanes 0..3 own a second entry
        u64 a0, a1, b0 = tag, b1 = tag;
        for (;;) {
            a0 = vload64(&g_pub_min[lane]);
            a1 = vload64(&g_pub_max[lane]);
            bool ok = (a0 >= tag) & (a1 >= tag);
            if (e2 < NBLK) {
                b0 = vload64(&g_pub_min[e2]);
                b1 = vload64(&g_pub_max[e2]);
                ok &= (b0 >= tag) & (b1 >= tag);
            }
            if (__all_sync(0xffffffffu, ok)) break;
        }
        float gmn = __int_as_float((int)(unsigned)a0);
        float gmx = __int_as_float((int)(unsigned)a1);
        if (e2 < NBLK) {
            gmn = fminf(gmn, __int_as_float((int)(unsigned)b0));
            gmx = fmaxf(gmx, __int_as_float((int)(unsigned)b1));
        }
#pragma unroll
        for (int o = 16; o; o >>= 1) {
            gmn = fminf(gmn, __shfl_xor_sync(0xffffffffu, gmn, o));
            gmx = fmaxf(gmx, __shfl_xor_sync(0xffffffffu, gmx, o));
        }
        if (lane == 0) s_th = (gmx - gmn) / 96.0f;  // exact f32 order as ref
    }
    __syncthreads();
    const float th = s_th;

    // ---- edge test: one candidate per thread; ballot = in-order edge bits ----
    const bool bit = valid && (mw != 0u) && (fabsf(ndv - dv) <= th);
    const unsigned ballot = __ballot_sync(0xffffffffu, bit);
    if (lane == 0) sws[w] = __popc(ballot);

    // order sentinel-fill stores before the cross-block count publication
    __threadfence();
    __syncthreads();

    // ---- warp 0: block scan of 32 warp counts, publish total, poll, prefix --
    if (w == 0) {
        const int val = sws[lane];
        int incl = val;
#pragma unroll
        for (int o = 1; o < 32; o <<= 1) {
            int u = __shfl_up_sync(0xffffffffu, incl, o);
            if (lane >= o) incl += u;
        }
        sws[lane] = incl - val;             // exclusive warp prefix
        const int total = __shfl_sync(0xffffffffu, incl, 31);
        if (lane == 31) g_pub_cnt[b] = tag | (u64)(unsigned)total;

        const int e2 = lane + 32;
        u64 a0, b0 = tag;
        for (;;) {
            a0 = vload64(&g_pub_cnt[lane]);
            bool ok = (a0 >= tag);
            if (e2 < NBLK) {
                b0 = vload64(&g_pub_cnt[e2]);
                ok &= (b0 >= tag);
            }
            if (__all_sync(0xffffffffu, ok)) break;
        }
        int s = (lane < b) ? (int)(unsigned)a0 : 0;
        if (e2 < b) s += (int)(unsigned)b0;
#pragma unroll
        for (int o = 16; o; o >>= 1) s += __shfl_xor_sync(0xffffffffu, s, o);
        if (lane == 0) s_base = s;
    }
    __syncthreads();

    // ---- parallel scatter: each edge-thread writes its own pair ----
    if (bit) {
        const int pos = s_base + sws[w] + __popc(ballot & ((1u << lane) - 1u));
        out[pos]             = (float)l;
        out[MAX_EDGES + pos] = (float)nl;
    }
}

// --------------------------------------------------------------------------
extern "C" void kernel_launch(void* const* d_in, const int* in_sizes, int n_in,
                              void* d_out, int out_size) {
    // Resolve inputs by element count (unique per input):
    //   d_coarse = 36864 (f32), noise = 9216 (f32),
    //   dropout_mask = 84934656 (bool materialized as 4-byte 0/1 words),
    //   R_scale = 1 (unused)
    const float*        dc    = nullptr;
    const float*        noise = nullptr;
    const unsigned int* mask  = nullptr;

    for (int i = 0; i < n_in; i++) {
        int s = in_sizes[i];
        if (s == MASK_ELEMS) mask  = (const unsigned int*)d_in[i];
        else if (s == 36864) dc    = (const float*)d_in[i];
        else if (s == 9216)  noise = (const float*)d_in[i];
    }

    float* out = (float*)d_out;   // [2, 36864] compared as float32

    k_fused<<<NBLK, 1024>>>(dc, noise, mask, out);
}

// round 16
// speedup vs baseline: 1.4571x; 1.4571x over previous
#include <cuda_runtime.h>

// Problem constants
#define GRID_M     96
#define NUM_NODES  9216          // 96*96
#define MAX_EDGES  36864         // 4*NUM_NODES
#define IMG_W      192
#define MASK_ELEMS 84934656      // 9216*9216
#define NBLK       36            // 36 blocks x 256 threads; all co-resident

typedef unsigned long long u64;

// Scratch (no allocations, no resets, NO shared atomics):
// Each publication slot is written exactly once per call by its owning block.
// Tag = (previous high word + 1) << 32, derived from the block's OWN slot, so
// all blocks compute the same per-call tag with zero contention. Stale values
// are self-identifying (tag too small), so no fences/reset choreography.
__device__ u64 g_pub_min[NBLK];   // tag | float_bits(block min)
__device__ u64 g_pub_max[NBLK];   // tag | float_bits(block max)
__device__ u64 g_pub_cnt[NBLK];   // tag | block edge count

__device__ __forceinline__ u64 vload64(const u64* p) {
    return *((volatile const u64*)p);
}

// pool+noise value of node (i,j): bit-identical everywhere (same op order).
__device__ __forceinline__ float node_d(const float* __restrict__ dc,
                                        const float* __restrict__ noise,
                                        int i, int j) {
    const float2* r0 = reinterpret_cast<const float2*>(dc + (2 * i) * IMG_W);
    const float2* r1 = reinterpret_cast<const float2*>(dc + (2 * i + 1) * IMG_W);
    float2 a = r0[j];
    float2 c = r1[j];
    return fmaxf(fmaxf(a.x, a.y), fmaxf(c.x, c.y)) + noise[i * GRID_M + j];
}

// --------------------------------------------------------------------------
// Single fused kernel: 36 blocks x 256 threads, one node per thread.
// Two data-carrying tagged-flag exchanges (min/max, then counts); the poll
// that detects completion simultaneously delivers the payloads.
// --------------------------------------------------------------------------
__global__ __launch_bounds__(256, 1)
void k_fused(const float* __restrict__ dc, const float* __restrict__ noise,
             const unsigned int* __restrict__ mask, float* __restrict__ out) {
    __shared__ float smn[8], smx[8];
    __shared__ int   sws[8];
    __shared__ float s_th;
    __shared__ int   s_base;
    __shared__ u64   s_tag;

    const int b    = blockIdx.x;
    const int t    = threadIdx.x;
    const int lane = t & 31;
    const int w    = t >> 5;
    const int l    = b * 256 + t;          // node id, 0..9215
    const int i    = l / GRID_M;
    const int j    = l - i * GRID_M;

    // ---- per-call tag from our OWN previous publication (no atomics) ----
    if (t == 0) {
        u64 prev = vload64(&g_pub_min[b]);          // overlaps the loads below
        s_tag = ((prev >> 32) + 1ull) << 32;
    }

    // ---- Issue ALL independent scattered loads up front ----
    const bool up = (i > 0), dn = (i < GRID_M - 1);
    const bool lt = (j > 0), rt = (j < GRID_M - 1);
    const unsigned rowbase = (unsigned)l * (unsigned)NUM_NODES;

    unsigned mk0 = 0, mk1 = 0, mk2 = 0, mk3 = 0;   // dropout words (0/1)
    if (up && lt) mk0 = mask[rowbase + (unsigned)(l - 97)];
    if (up && rt) mk1 = mask[rowbase + (unsigned)(l - 95)];
    if (dn && lt) mk2 = mask[rowbase + (unsigned)(l + 95)];
    if (dn && rt) mk3 = mask[rowbase + (unsigned)(l + 97)];

    // own pooled value (pre-noise) + d
    float v;
    {
        const float2* r0 = reinterpret_cast<const float2*>(dc + (2 * i) * IMG_W);
        const float2* r1 = reinterpret_cast<const float2*>(dc + (2 * i + 1) * IMG_W);
        float2 a = r0[j];
        float2 c = r1[j];
        v = fmaxf(fmaxf(a.x, a.y), fmaxf(c.x, c.y));
    }
    const float dv = v + noise[l];

    // neighbor d values (bit-identical recomputation)
    float n0 = 0.f, n1 = 0.f, n2 = 0.f, n3 = 0.f;
    if (up && lt) n0 = node_d(dc, noise, i - 1, j - 1);
    if (up && rt) n1 = node_d(dc, noise, i - 1, j + 1);
    if (dn && lt) n2 = node_d(dc, noise, i + 1, j - 1);
    if (dn && rt) n3 = node_d(dc, noise, i + 1, j + 1);

    // ---- Sentinel fill (73728 floats = 2 x float4 per thread) ----
    {
        float4 s4 = make_float4((float)NUM_NODES, (float)NUM_NODES,
                                (float)NUM_NODES, (float)NUM_NODES);
        float4* o4 = reinterpret_cast<float4*>(out);
        o4[l]             = s4;
        o4[l + NUM_NODES] = s4;
    }

    // ---- Block min/max over own 256 pooled values ----
    {
        float mn = v, mx = v;
#pragma unroll
        for (int o = 16; o; o >>= 1) {
            mn = fminf(mn, __shfl_xor_sync(0xffffffffu, mn, o));
            mx = fmaxf(mx, __shfl_xor_sync(0xffffffffu, mx, o));
        }
        if (lane == 0) { smn[w] = mn; smx[w] = mx; }
    }
    __syncthreads();                       // also publishes s_tag

    const u64 tag = s_tag;

    // thread 0: fold 8 warp partials, publish tagged min/max (single words)
    if (t == 0) {
        float mn = smn[0], mx = smx[0];
#pragma unroll
        for (int k = 1; k < 8; k++) {
            mn = fminf(mn, smn[k]);
            mx = fmaxf(mx, smx[k]);
        }
        g_pub_min[b] = tag | (u64)(unsigned)__float_as_int(mn);
        g_pub_max[b] = tag | (u64)(unsigned)__float_as_int(mx);
    }

    // warp 0 polls all 36 min/max pairs; payload arrives with the poll
    if (w == 0) {
        const int e2 = lane + 32;          // lanes 0..3 own a second entry
        u64 a0, a1, b0 = tag, b1 = tag;
        for (;;) {
            a0 = vload64(&g_pub_min[lane]);
            a1 = vload64(&g_pub_max[lane]);
            bool ok = (a0 >= tag) & (a1 >= tag);
            if (e2 < NBLK) {
                b0 = vload64(&g_pub_min[e2]);
                b1 = vload64(&g_pub_max[e2]);
                ok &= (b0 >= tag) & (b1 >= tag);
            }
            if (__all_sync(0xffffffffu, ok)) break;
        }
        float mn = __int_as_float((int)(unsigned)a0);
        float mx = __int_as_float((int)(unsigned)a1);
        if (e2 < NBLK) {
            mn = fminf(mn, __int_as_float((int)(unsigned)b0));
            mx = fmaxf(mx, __int_as_float((int)(unsigned)b1));
        }
#pragma unroll
        for (int o = 16; o; o >>= 1) {
            mn = fminf(mn, __shfl_xor_sync(0xffffffffu, mn, o));
            mx = fmaxf(mx, __shfl_xor_sync(0xffffffffu, mx, o));
        }
        if (lane == 0) s_th = (mx - mn) / 96.0f;  // exact f32 order as reference
    }
    __syncthreads();
    const float th = s_th;

    // ---- Edge tests (all operands already in registers) ----
    unsigned m = 0;
    if (mk0 && fabsf(n0 - dv) <= th) m |= 1u;   // (i-1,j-1)
    if (mk1 && fabsf(n1 - dv) <= th) m |= 2u;   // (i-1,j+1)
    if (mk2 && fabsf(n2 - dv) <= th) m |= 4u;   // (i+1,j-1)
    if (mk3 && fabsf(n3 - dv) <= th) m |= 8u;   // (i+1,j+1)

    // ---- Block exclusive scan + total ----
    const int c = __popc(m);
    int incl = c;
#pragma unroll
    for (int o = 1; o < 32; o <<= 1) {
        int u = __shfl_up_sync(0xffffffffu, incl, o);
        if (lane >= o) incl += u;
    }
    if (lane == 31) sws[w] = incl;
    __syncthreads();
    int wbase = 0, total = 0;
#pragma unroll
    for (int k = 0; k < 8; k++) {
        int sv = sws[k];
        wbase += (k < w) ? sv : 0;
        total += sv;
    }
    const int excl = wbase + (incl - c);

    // ---- Publish tagged count; warp 0 polls all 36 and prefixes them ----
    if (t == 0) g_pub_cnt[b] = tag | (u64)(unsigned)total;

    if (w == 0) {
        const int e2 = lane + 32;
        u64 a0, b0 = tag;
        for (;;) {
            a0 = vload64(&g_pub_cnt[lane]);
            bool ok = (a0 >= tag);
            if (e2 < NBLK) {
                b0 = vload64(&g_pub_cnt[e2]);
                ok &= (b0 >= tag);
            }
            if (__all_sync(0xffffffffu, ok)) break;
        }
        int s = (lane < b) ? (int)(unsigned)a0 : 0;
        if (e2 < b) s += (int)(unsigned)b0;
#pragma unroll
        for (int o = 16; o; o >>= 1) s += __shfl_xor_sync(0xffffffffu, s, o);
        if (lane == 0) s_base = s;
    }
    __syncthreads();

    // ---- Scatter (jnp.nonzero order) over pre-written sentinels ----
    int pos = s_base + excl;
    const float fl = (float)l;
    if (m & 1u) { out[pos] = fl; out[MAX_EDGES + pos] = (float)(l - 97); pos++; }
    if (m & 2u) { out[pos] = fl; out[MAX_EDGES + pos] = (float)(l - 95); pos++; }
    if (m & 4u) { out[pos] = fl; out[MAX_EDGES + pos] = (float)(l + 95); pos++; }
    if (m & 8u) { out[pos] = fl; out[MAX_EDGES + pos] = (float)(l + 97); pos++; }
}

// --------------------------------------------------------------------------
extern "C" void kernel_launch(void* const* d_in, const int* in_sizes, int n_in,
                              void* d_out, int out_size) {
    // Resolve inputs by element count (unique per input):
    //   d_coarse = 36864 (f32), noise = 9216 (f32),
    //   dropout_mask = 84934656 (bool materialized as 4-byte 0/1 words),
    //   R_scale = 1 (unused)
    const float*        dc    = nullptr;
    const float*        noise = nullptr;
    const unsigned int* mask  = nullptr;

    for (int i = 0; i < n_in; i++) {
        int s = in_sizes[i];
        if (s == MASK_ELEMS) mask  = (const unsigned int*)d_in[i];
        else if (s == 36864) dc    = (const float*)d_in[i];
        else if (s == 9216)  noise = (const float*)d_in[i];
    }

    float* out = (float*)d_out;   // [2, 36864] compared as float32

    k_fused<<<NBLK, 256>>>(dc, noise, mask, out);
}